// round 1
// baseline (speedup 1.0000x reference)
#include <cuda_runtime.h>
#include <math_constants.h>

#define N_EMBED 64

// Scratch (no allocations allowed): transformed codebook + likelihood accumulator.
__device__ float4 g_cdf[N_EMBED];    // (c, d, f, 0) with log2e and sigma folded in
__device__ float2 g_emb[N_EMBED];    // raw codewords for the hard-quantize gather
__device__ float  g_like[N_EMBED];   // un-normalized likelihood sums

// ---------------------------------------------------------------------------
// Kernel 1: transform codebook, zero accumulators.
// logit2_j = log2e * ( 2*sigma*(p . e_j) - sigma*|e_j|^2 )
// ---------------------------------------------------------------------------
__global__ void jsccq_prep(const float* __restrict__ embed, int n_embed) {
    int j = threadIdx.x;
    if (j < n_embed) {
        const float SIGMA = 10.0f;
        const float L2E   = 1.4426950408889634f;
        float ex = embed[2 * j + 0];
        float ey = embed[2 * j + 1];
        float s  = SIGMA * L2E;
        g_cdf[j] = make_float4(2.0f * s * ex,
                               2.0f * s * ey,
                               -s * (ex * ex + ey * ey),
                               0.0f);
        g_emb[j]  = make_float2(ex, ey);
        g_like[j] = 0.0f;
    }
}

// ---------------------------------------------------------------------------
// Kernel 2: per-point argmax gather + softmax likelihood accumulation.
// ---------------------------------------------------------------------------
__global__ __launch_bounds__(128, 3)
void jsccq_main(const float* __restrict__ x, float* __restrict__ out_q, int npts) {
    __shared__ float4 s_cdf[N_EMBED];
    __shared__ float2 s_emb[N_EMBED];
    __shared__ float  s_like[N_EMBED];

    const int tid = threadIdx.x;
    if (tid < N_EMBED) {
        s_cdf[tid]  = g_cdf[tid];
        s_emb[tid]  = g_emb[tid];
        s_like[tid] = 0.0f;
    }
    __syncthreads();

    float acc[N_EMBED];
#pragma unroll
    for (int j = 0; j < N_EMBED; j++) acc[j] = 0.0f;

    const float2* __restrict__ pts  = reinterpret_cast<const float2*>(x);
    float2* __restrict__       outq = reinterpret_cast<float2*>(out_q);

    const int stride = gridDim.x * blockDim.x;
    for (int n = blockIdx.x * blockDim.x + tid; n < npts; n += stride) {
        float2 p = pts[n];

        float e[N_EMBED];
        // Two interleaved max/argmax chains to halve the serial dep chain.
        float m0 = -CUDART_INF_F, m1 = -CUDART_INF_F;
        int   b0 = 0, b1 = 1;
#pragma unroll
        for (int j = 0; j < N_EMBED; j += 2) {
            float4 c0 = s_cdf[j];
            float4 c1 = s_cdf[j + 1];
            float l0 = fmaf(p.x, c0.x, fmaf(p.y, c0.y, c0.z));
            float l1 = fmaf(p.x, c1.x, fmaf(p.y, c1.y, c1.z));
            e[j]     = l0;
            e[j + 1] = l1;
            if (l0 > m0) { m0 = l0; b0 = j; }
            if (l1 > m1) { m1 = l1; b1 = j + 1; }
        }
        float m  = fmaxf(m0, m1);
        int   bi = (m1 > m0) ? b1 : b0;

        // exps (single MUFU.EX2 each; log2e already folded into constants)
        float sum0 = 0.0f, sum1 = 0.0f, sum2 = 0.0f, sum3 = 0.0f;
#pragma unroll
        for (int j = 0; j < N_EMBED; j += 4) {
            float v0 = exp2f(e[j + 0] - m);
            float v1 = exp2f(e[j + 1] - m);
            float v2 = exp2f(e[j + 2] - m);
            float v3 = exp2f(e[j + 3] - m);
            e[j + 0] = v0; e[j + 1] = v1; e[j + 2] = v2; e[j + 3] = v3;
            sum0 += v0; sum1 += v1; sum2 += v2; sum3 += v3;
        }
        float inv = 1.0f / ((sum0 + sum1) + (sum2 + sum3));

#pragma unroll
        for (int j = 0; j < N_EMBED; j++)
            acc[j] = fmaf(e[j], inv, acc[j]);

        // hard quantize: straight-through forward value == codeword of argmax
        outq[n] = s_emb[bi];
    }

    // Reduce likelihood partial sums: warp shuffle -> shared -> global.
#pragma unroll
    for (int j = 0; j < N_EMBED; j++) {
        float v = acc[j];
#pragma unroll
        for (int o = 16; o > 0; o >>= 1)
            v += __shfl_down_sync(0xffffffffu, v, o);
        if ((tid & 31) == 0)
            atomicAdd(&s_like[j], v);
    }
    __syncthreads();
    if (tid < N_EMBED)
        atomicAdd(&g_like[tid], s_like[tid]);
}

// ---------------------------------------------------------------------------
// Kernel 3: finalize likelihoods (mean) into the tail of d_out.
// ---------------------------------------------------------------------------
__global__ void jsccq_fin(float* __restrict__ out_like, float invN, int n_embed) {
    int j = threadIdx.x;
    if (j < n_embed)
        out_like[j] = g_like[j] * invN;
}

extern "C" void kernel_launch(void* const* d_in, const int* in_sizes, int n_in,
                              void* d_out, int out_size) {
    const float* x     = (const float*)d_in[0];   // [64,32,32,32] fp32
    const float* embed = (const float*)d_in[1];   // [64,2] fp32
    float* out = (float*)d_out;

    const int npts    = in_sizes[0] / 2;          // 1,048,576 points
    const int n_embed = in_sizes[1] / 2;          // 64

    jsccq_prep<<<1, N_EMBED>>>(embed, n_embed);

    const int threads = 128;
    const int blocks  = 444;                      // 3 blocks/SM * 148 SMs
    jsccq_main<<<blocks, threads>>>(x, out, npts);

    // quantize occupies the first 2*npts floats; likelihoods (if present) follow
    if (out_size >= 2 * npts + n_embed) {
        jsccq_fin<<<1, N_EMBED>>>(out + 2 * npts, 1.0f / (float)npts, n_embed);
    }
}

// round 2
// speedup vs baseline: 1.4075x; 1.4075x over previous
#include <cuda_runtime.h>
#include <math_constants.h>

#define N_EMBED   64
#define NBLK      592          // 4 blocks/SM * 148 SMs
#define NTHREADS  128
#define NGROUPS   (NBLK * NTHREADS / 4)   // 4-lane groups

// Per-block likelihood partials, transposed: [codeword][block]
__device__ float g_part[N_EMBED * NBLK];

__device__ __forceinline__ float ex2(float x) {
    float r;
    asm("ex2.approx.f32 %0, %1;" : "=f"(r) : "f"(x));
    return r;
}
__device__ __forceinline__ float rcp(float x) {
    float r;
    asm("rcp.approx.f32 %0, %1;" : "=f"(r) : "f"(x));
    return r;
}

// ---------------------------------------------------------------------------
// Main kernel: each 4-lane group handles one point per iteration.
// Lane g of the group owns codewords [g*16, g*16+16) with constants in regs.
// logit2_j = log2e * sigma * (2*(p.e_j) - |e_j|^2)   (per-point |p|^2 cancels)
// ---------------------------------------------------------------------------
__global__ __launch_bounds__(NTHREADS, 4)
void jsccq_main(const float* __restrict__ x, const float* __restrict__ embed,
                float* __restrict__ out_q, int npts) {
    __shared__ float  s_cx[N_EMBED], s_cy[N_EMBED], s_cz[N_EMBED];
    __shared__ float2 s_emb[N_EMBED];
    __shared__ float  s_like[N_EMBED];

    const int tid = threadIdx.x;
    if (tid < N_EMBED) {
        const float s = 10.0f * 1.4426950408889634f;   // sigma * log2(e)
        float ex = embed[2 * tid + 0];
        float ey = embed[2 * tid + 1];
        s_cx[tid]  = 2.0f * s * ex;
        s_cy[tid]  = 2.0f * s * ey;
        s_cz[tid]  = -s * (ex * ex + ey * ey);
        s_emb[tid] = make_float2(ex, ey);
        s_like[tid] = 0.0f;
    }
    __syncthreads();

    const int lane_in_grp = tid & 3;
    const int base = lane_in_grp * 16;

    // Register-resident codebook slice (48 regs)
    float cx[16], cy[16], cz[16];
#pragma unroll
    for (int k = 0; k < 16; k++) {
        cx[k] = s_cx[base + k];
        cy[k] = s_cy[base + k];
        cz[k] = s_cz[base + k];
    }

    float acc[16];
#pragma unroll
    for (int k = 0; k < 16; k++) acc[k] = 0.0f;

    const float2* __restrict__ pts = reinterpret_cast<const float2*>(x);
    float2* __restrict__       oq  = reinterpret_cast<float2*>(out_q);

    const int gid   = (blockIdx.x * NTHREADS + tid) >> 2;
    const int iters = (npts + NGROUPS - 1) / NGROUPS;   // uniform trip count

    for (int i = 0; i < iters; i++) {
        const int n = gid + i * NGROUPS;
        const bool act = (n < npts);
        float2 p = act ? pts[n] : make_float2(0.0f, 0.0f);

        // --- logits + local max/argmax (2 interleaved chains) ---
        float e[16];
        float m0 = -CUDART_INF_F, m1 = -CUDART_INF_F;
        int   b0 = base, b1 = base + 1;
#pragma unroll
        for (int k = 0; k < 16; k += 2) {
            float l0 = fmaf(p.x, cx[k],     fmaf(p.y, cy[k],     cz[k]));
            float l1 = fmaf(p.x, cx[k + 1], fmaf(p.y, cy[k + 1], cz[k + 1]));
            e[k]     = l0;
            e[k + 1] = l1;
            if (l0 > m0) { m0 = l0; b0 = base + k; }
            if (l1 > m1) { m1 = l1; b1 = base + k + 1; }
        }
        float m  = m0;
        int   bi = b0;
        if (m1 > m0) { m = m1; bi = b1; }

        // --- cross-lane max/argmax within 4-lane group (xor 1, 2) ---
#pragma unroll
        for (int o = 1; o <= 2; o <<= 1) {
            float om = __shfl_xor_sync(0xffffffffu, m,  o);
            int   ob = __shfl_xor_sync(0xffffffffu, bi, o);
            if (om > m || (om == m && ob < bi)) { m = om; bi = ob; }
        }

        // --- exps + partial sum (4 chains) ---
        float s0 = 0.0f, s1 = 0.0f, s2 = 0.0f, s3 = 0.0f;
#pragma unroll
        for (int k = 0; k < 16; k += 4) {
            float v0 = ex2(e[k + 0] - m);
            float v1 = ex2(e[k + 1] - m);
            float v2 = ex2(e[k + 2] - m);
            float v3 = ex2(e[k + 3] - m);
            e[k + 0] = v0; e[k + 1] = v1; e[k + 2] = v2; e[k + 3] = v3;
            s0 += v0; s1 += v1; s2 += v2; s3 += v3;
        }
        float ssum = (s0 + s1) + (s2 + s3);
        ssum += __shfl_xor_sync(0xffffffffu, ssum, 1);
        ssum += __shfl_xor_sync(0xffffffffu, ssum, 2);

        const float inv = act ? rcp(ssum) : 0.0f;   // inactive -> contributes 0
#pragma unroll
        for (int k = 0; k < 16; k++)
            acc[k] = fmaf(e[k], inv, acc[k]);

        // hard quantize (straight-through forward value = argmax codeword)
        if (act && lane_in_grp == 0)
            oq[n] = s_emb[bi];
    }

    // --- likelihood reduction: lanes with same role (xor 4, 8, 16) ---
#pragma unroll
    for (int k = 0; k < 16; k++) {
        float v = acc[k];
        v += __shfl_xor_sync(0xffffffffu, v, 4);
        v += __shfl_xor_sync(0xffffffffu, v, 8);
        v += __shfl_xor_sync(0xffffffffu, v, 16);
        if ((tid & 31) < 4)
            atomicAdd(&s_like[base + k], v);
    }
    __syncthreads();
    if (tid < N_EMBED)
        g_part[tid * NBLK + blockIdx.x] = s_like[tid];
}

// ---------------------------------------------------------------------------
// Finalize: reduce per-block partials -> mean likelihoods.
// 32 warps; warp w handles codewords w and w+32 (coalesced over blocks).
// ---------------------------------------------------------------------------
__global__ void jsccq_fin(float* __restrict__ out_like, float invN) {
    const int wid  = threadIdx.x >> 5;
    const int lane = threadIdx.x & 31;
#pragma unroll
    for (int half = 0; half < 2; half++) {
        const int cw = wid + half * 32;
        float s = 0.0f;
        for (int b = lane; b < NBLK; b += 32)
            s += g_part[cw * NBLK + b];
#pragma unroll
        for (int o = 16; o > 0; o >>= 1)
            s += __shfl_xor_sync(0xffffffffu, s, o);
        if (lane == 0)
            out_like[cw] = s * invN;
    }
}

extern "C" void kernel_launch(void* const* d_in, const int* in_sizes, int n_in,
                              void* d_out, int out_size) {
    const float* x     = (const float*)d_in[0];   // [64,32,32,32] fp32
    const float* embed = (const float*)d_in[1];   // [64,2]        fp32
    float* out = (float*)d_out;

    const int npts = in_sizes[0] / 2;             // 1,048,576 points

    jsccq_main<<<NBLK, NTHREADS>>>(x, embed, out, npts);

    if (out_size >= 2 * npts + N_EMBED)
        jsccq_fin<<<1, 1024>>>(out + 2 * npts, 1.0f / (float)npts);
}